// round 11
// baseline (speedup 1.0000x reference)
#include <cuda_runtime.h>
#include <cuda_fp16.h>
#include <cstdint>
#include <cstddef>

// ---------------- problem sizes ----------------
#define MDIM 8192
#define NDIM 4096
#define KDIM 4096
#define MT 128          // CTA tile M
#define NT 128          // CTA tile N
#define KC 64           // K elements per chunk (fp16 -> 128B rows)
#define NCHUNK (KDIM / KC)          // 64
#define STAGES 3
#define A_TILE 16384                // 128 rows x 128B
#define B_TILE 16384                // 128 rows x 128B
#define STAGE_BYTES (A_TILE + B_TILE)       // 32768
#define SMEM_BYTES (STAGES * STAGE_BYTES)   // 98304 -> 2 CTAs/SM

// ---------------- device scratch (no allocation allowed) ----------------
__device__ __align__(128) __half g_X[(size_t)MDIM * KDIM];
__device__ __align__(128) __half g_W[(size_t)NDIM * KDIM];

// ---------------- PTX helpers (base sm_103 target only) -------------------
static __device__ __forceinline__ uint32_t smem_u32(const void* p) {
    uint32_t a;
    asm("{ .reg .u64 t; cvta.to.shared.u64 t, %1; cvt.u32.u64 %0, t; }" : "=r"(a) : "l"(p));
    return a;
}

#define CP16(dst, src) \
    asm volatile("cp.async.cg.shared.global [%0], [%1], 16;" :: "r"((uint32_t)(dst)), "l"(src) : "memory")
#define CP_COMMIT() asm volatile("cp.async.commit_group;" ::: "memory")
#define CP_WAIT(n)  asm volatile("cp.async.wait_group %0;" :: "n"(n) : "memory")

#define LDSM4(r0, r1, r2, r3, addr) \
    asm volatile("ldmatrix.sync.aligned.m8n8.x4.shared.b16 {%0,%1,%2,%3}, [%4];" \
                 : "=r"(r0), "=r"(r1), "=r"(r2), "=r"(r3) : "r"(addr))

// f16 MMA, fp32 accumulate: D[16x8] += A[16x16] * B[16x8]
#define MMA_F16(d, a0, a1, a2, a3, b0, b1) \
    asm volatile("mma.sync.aligned.m16n8k16.row.col.f32.f16.f16.f32 " \
                 "{%0,%1,%2,%3}, {%4,%5,%6,%7}, {%8,%9}, {%0,%1,%2,%3};" \
                 : "+f"((d)[0]), "+f"((d)[1]), "+f"((d)[2]), "+f"((d)[3]) \
                 : "r"(a0), "r"(a1), "r"(a2), "r"(a3), "r"(b0), "r"(b1))

// ---------------- fused prepass: x fp32->fp16, w int32->fp16 --------------
#define NX4 ((size_t)MDIM * KDIM / 4)
#define NW4 ((size_t)NDIM * KDIM / 4)
__global__ void __launch_bounds__(256) cvt_kernel(const float* __restrict__ x,
                                                  const int* __restrict__ w) {
    const float4* __restrict__ x4 = (const float4*)x;
    const int4* __restrict__ w4 = (const int4*)w;
    uint2* __restrict__ dx = (uint2*)g_X;
    uint2* __restrict__ dw = (uint2*)g_W;
    const size_t total = NX4 + NW4;
    size_t stride = (size_t)gridDim.x * blockDim.x;
    for (size_t i = (size_t)blockIdx.x * blockDim.x + threadIdx.x; i < total; i += stride) {
        if (i < NX4) {
            float4 v = x4[i];
            uint32_t h0 = __half_as_ushort(__float2half_rn(v.x));
            uint32_t h1 = __half_as_ushort(__float2half_rn(v.y));
            uint32_t h2 = __half_as_ushort(__float2half_rn(v.z));
            uint32_t h3 = __half_as_ushort(__float2half_rn(v.w));
            uint2 p;
            p.x = h0 | (h1 << 16);
            p.y = h2 | (h3 << 16);
            dx[i] = p;
        } else {
            const size_t j = i - NX4;
            int4 v = w4[j];
            uint32_t h0 = __half_as_ushort(__int2half_rn(v.x));
            uint32_t h1 = __half_as_ushort(__int2half_rn(v.y));
            uint32_t h2 = __half_as_ushort(__int2half_rn(v.z));
            uint32_t h3 = __half_as_ushort(__int2half_rn(v.w));
            uint2 p;
            p.x = h0 | (h1 << 16);
            p.y = h2 | (h3 << 16);
            dw[j] = p;
        }
    }
}

// ---------------- main GEMM: mma.sync f16 (f32 acc), cp.async 3-stage -----
// 128 threads = 4 warps. CTA tile 128(M) x 128(N); warp tile 64(M) x 64(N).
// 2 CTAs/SM. The produce burst (16 cp.async/thread) is spread across the 4
// k-steps so LDGSTS issue lands under the MMA shadow instead of colliding
// with the post-barrier LDSM preamble on the MIO path.
__global__ void __launch_bounds__(128, 2) qgemm_kernel(
    const float* __restrict__ scale,
    const float* __restrict__ bias,
    float* __restrict__ out
) {
    extern __shared__ char smem[];
    const uint32_t sbase = smem_u32(smem);
    const int tid = threadIdx.x;
    const int m0 = blockIdx.y * MT;
    const int n0 = blockIdx.x * NT;

    const int lane = tid & 31;
    const int wid = tid >> 5;
    const int wm = wid & 1;      // M half (64 rows)
    const int wn = wid >> 1;     // N half (64 cols)

    // gmem byte-bases (row stride = KDIM * 2 bytes = 8192 = 1<<13)
    const char* pX = (const char*)g_X + ((size_t)m0 << 13);
    const char* pW = (const char*)g_W + ((size_t)n0 << 13);

    // ldmatrix address components
    const int rA = 64 * wm + (lane & 7) + ((lane >> 3) & 1) * 8;
    const int kaddA = ((lane >> 4) & 1) * 16;
    const uint32_t xmA = (uint32_t)((lane & 7) << 4);
    const int nrb = 64 * wn + (lane & 7) + ((lane >> 4) & 1) * 8;
    const int kaddB = ((lane >> 3) & 1) * 16;
    const uint32_t xmB = (uint32_t)((lane & 7) << 4);

    float acc[4][8][4];
    #pragma unroll
    for (int a = 0; a < 4; ++a)
        #pragma unroll
        for (int b = 0; b < 8; ++b)
            #pragma unroll
            for (int c = 0; c < 4; ++c) acc[a][b][c] = 0.0f;

    // one 16B A-granule + one 16B B-granule for index i (0..7)
    auto load_pair = [&](uint32_t stn, uint32_t ko, int i) {
        const int g = tid + i * 128;
        const int row = g >> 3;
        const int col = (g & 7) << 4;
        const uint32_t soff = (uint32_t)(row * 128) + ((uint32_t)col ^ (uint32_t)((row & 7) << 4));
        const size_t goff = ((size_t)row << 13) + ko + col;
        CP16(stn + soff,          pX + goff);
        CP16(stn + A_TILE + soff, pW + goff);
    };

    // full stage load (prologue only)
    auto load_stage = [&](int stg, int c) {
        const uint32_t st = sbase + (uint32_t)stg * STAGE_BYTES;
        const uint32_t ko = (uint32_t)c << 7;
        #pragma unroll
        for (int i = 0; i < 8; ++i) load_pair(st, ko, i);
    };

    // ---- prologue: stages 0,1 ----
    load_stage(0, 0); CP_COMMIT();
    load_stage(1, 1); CP_COMMIT();

    // ---- mainloop ----
    int s_cur = 0;          // stage being computed
    int s_nxt = 2;          // stage to fill with chunk c+2
    for (int c = 0; c < NCHUNK; ++c) {
        CP_WAIT(1);
        __syncthreads();

        const uint32_t st = sbase + (uint32_t)s_cur * STAGE_BYTES;
        const uint32_t aA = st + (uint32_t)(rA * 128);
        const uint32_t aB = st + A_TILE + (uint32_t)(nrb * 128);
        const bool pf = (c + 2 < NCHUNK);
        const uint32_t stn = sbase + (uint32_t)s_nxt * STAGE_BYTES;
        const uint32_t ko2 = (uint32_t)(c + 2) << 7;

        uint32_t af[4][4];
        uint32_t bf[4][4];

        #pragma unroll
        for (int ks = 0; ks < 4; ++ks) {
            const uint32_t kA = ((uint32_t)(ks * 32 + kaddA)) ^ xmA;
            const uint32_t kB = ((uint32_t)(ks * 32 + kaddB)) ^ xmB;
            #pragma unroll
            for (int mb = 0; mb < 4; ++mb)
                LDSM4(af[mb][0], af[mb][1], af[mb][2], af[mb][3],
                      aA + (uint32_t)(mb * 16 * 128) + kA);
            #pragma unroll
            for (int p = 0; p < 4; ++p)
                LDSM4(bf[p][0], bf[p][1], bf[p][2], bf[p][3],
                      aB + (uint32_t)(p * 16 * 128) + kB);

            // spread produce: 2 granule-pairs per k-step, under the MMA shadow
            if (pf) {
                load_pair(stn, ko2, 2 * ks);
                load_pair(stn, ko2, 2 * ks + 1);
            }

            #pragma unroll
            for (int mb = 0; mb < 4; ++mb) {
                #pragma unroll
                for (int nt = 0; nt < 8; ++nt) {
                    const uint32_t b0 = bf[nt >> 1][(nt & 1) * 2];
                    const uint32_t b1 = bf[nt >> 1][(nt & 1) * 2 + 1];
                    MMA_F16(acc[mb][nt], af[mb][0], af[mb][1], af[mb][2], af[mb][3], b0, b1);
                }
            }
        }
        CP_COMMIT();    // one group per chunk (possibly empty on the tail)

        // rotate stages
        s_cur = (s_cur == 2) ? 0 : s_cur + 1;
        s_nxt = (s_nxt == 2) ? 0 : s_nxt + 1;
    }

    // ---- epilogue: y = scale[n] * acc + bias[n] ----
    const int ncol = n0 + 64 * wn + 2 * (lane & 3);
    const float* scn = scale + ncol;
    const float* bin = bias + ncol;
    #pragma unroll
    for (int mb = 0; mb < 4; ++mb) {
        const int mr0 = m0 + 64 * wm + 16 * mb + (lane >> 2);
        const int mr1 = mr0 + 8;
        float* o0 = out + (size_t)mr0 * NDIM + ncol;
        float* o1 = out + (size_t)mr1 * NDIM + ncol;
        #pragma unroll
        for (int nt = 0; nt < 8; ++nt) {
            const float2 ws = *(const float2*)(scn + 8 * nt);
            const float2 bb = *(const float2*)(bin + 8 * nt);
            float2 v0, v1;
            v0.x = ws.x * acc[mb][nt][0] + bb.x;
            v0.y = ws.y * acc[mb][nt][1] + bb.y;
            v1.x = ws.x * acc[mb][nt][2] + bb.x;
            v1.y = ws.y * acc[mb][nt][3] + bb.y;
            *(float2*)(o0 + 8 * nt) = v0;
            *(float2*)(o1 + 8 * nt) = v1;
        }
    }
}

// ---------------- launcher ----------------
extern "C" void kernel_launch(void* const* d_in, const int* in_sizes, int n_in,
                              void* d_out, int out_size) {
    const float* x     = (const float*)d_in[0];
    const int*   w     = (const int*)d_in[1];
    const float* scale = (const float*)d_in[2];
    const float* bias  = (const float*)d_in[3];
    float* out = (float*)d_out;

    cudaFuncSetAttribute(qgemm_kernel, cudaFuncAttributeMaxDynamicSharedMemorySize, SMEM_BYTES);

    cvt_kernel<<<4096, 256>>>(x, w);

    dim3 grid(NDIM / NT, MDIM / MT);   // (32, 64) = 2048 CTAs
    qgemm_kernel<<<grid, 128, SMEM_BYTES>>>(scale, bias, out);
}

// round 12
// speedup vs baseline: 1.0031x; 1.0031x over previous
#include <cuda_runtime.h>
#include <cuda_fp16.h>
#include <cstdint>
#include <cstddef>

// ---------------- problem sizes ----------------
#define MDIM 8192
#define NDIM 4096
#define KDIM 4096
#define MT 128          // CTA tile M
#define NT 128          // CTA tile N
#define KC 64           // K elements per chunk (fp16 -> 128B rows)
#define NCHUNK (KDIM / KC)          // 64
#define STAGES 3
#define A_TILE 16384                // 128 rows x 128B
#define B_TILE 16384                // 128 rows x 128B
#define STAGE_BYTES (A_TILE + B_TILE)       // 32768
#define SMEM_BYTES (STAGES * STAGE_BYTES)   // 98304 -> 2 CTAs/SM

// ---------------- device scratch (no allocation allowed) ----------------
__device__ __align__(128) __half g_X[(size_t)MDIM * KDIM];
__device__ __align__(128) __half g_W[(size_t)NDIM * KDIM];

// ---------------- PTX helpers (base sm_103 target only) -------------------
static __device__ __forceinline__ uint32_t smem_u32(const void* p) {
    uint32_t a;
    asm("{ .reg .u64 t; cvta.to.shared.u64 t, %1; cvt.u32.u64 %0, t; }" : "=r"(a) : "l"(p));
    return a;
}

#define CP16(dst, src) \
    asm volatile("cp.async.cg.shared.global [%0], [%1], 16;" :: "r"((uint32_t)(dst)), "l"(src) : "memory")
#define CP_COMMIT() asm volatile("cp.async.commit_group;" ::: "memory")
#define CP_WAIT(n)  asm volatile("cp.async.wait_group %0;" :: "n"(n) : "memory")

#define LDSM4(r0, r1, r2, r3, addr) \
    asm volatile("ldmatrix.sync.aligned.m8n8.x4.shared.b16 {%0,%1,%2,%3}, [%4];" \
                 : "=r"(r0), "=r"(r1), "=r"(r2), "=r"(r3) : "r"(addr))

// f16 MMA, fp32 accumulate: D[16x8] += A[16x16] * B[16x8]
#define MMA_F16(d, a0, a1, a2, a3, b0, b1) \
    asm volatile("mma.sync.aligned.m16n8k16.row.col.f32.f16.f16.f32 " \
                 "{%0,%1,%2,%3}, {%4,%5,%6,%7}, {%8,%9}, {%0,%1,%2,%3};" \
                 : "+f"((d)[0]), "+f"((d)[1]), "+f"((d)[2]), "+f"((d)[3]) \
                 : "r"(a0), "r"(a1), "r"(a2), "r"(a3), "r"(b0), "r"(b1))

// ---------------- fused prepass: x fp32->fp16, w int32->fp16 --------------
// 8 elements per thread per iteration: two 16B loads -> one 16B store.
#define NX8 ((size_t)MDIM * KDIM / 8)
#define NW8 ((size_t)NDIM * KDIM / 8)
__global__ void __launch_bounds__(256) cvt_kernel(const float* __restrict__ x,
                                                  const int* __restrict__ w) {
    const float4* __restrict__ x4 = (const float4*)x;
    const int4* __restrict__ w4 = (const int4*)w;
    uint4* __restrict__ dx = (uint4*)g_X;
    uint4* __restrict__ dw = (uint4*)g_W;
    const size_t total = NX8 + NW8;
    size_t stride = (size_t)gridDim.x * blockDim.x;
    for (size_t i = (size_t)blockIdx.x * blockDim.x + threadIdx.x; i < total; i += stride) {
        uint4 p;
        if (i < NX8) {
            float4 v0 = x4[2 * i];
            float4 v1 = x4[2 * i + 1];
            p.x = (uint32_t)__half_as_ushort(__float2half_rn(v0.x)) |
                  ((uint32_t)__half_as_ushort(__float2half_rn(v0.y)) << 16);
            p.y = (uint32_t)__half_as_ushort(__float2half_rn(v0.z)) |
                  ((uint32_t)__half_as_ushort(__float2half_rn(v0.w)) << 16);
            p.z = (uint32_t)__half_as_ushort(__float2half_rn(v1.x)) |
                  ((uint32_t)__half_as_ushort(__float2half_rn(v1.y)) << 16);
            p.w = (uint32_t)__half_as_ushort(__float2half_rn(v1.z)) |
                  ((uint32_t)__half_as_ushort(__float2half_rn(v1.w)) << 16);
            dx[i] = p;
        } else {
            const size_t j = i - NX8;
            int4 v0 = w4[2 * j];
            int4 v1 = w4[2 * j + 1];
            p.x = (uint32_t)__half_as_ushort(__int2half_rn(v0.x)) |
                  ((uint32_t)__half_as_ushort(__int2half_rn(v0.y)) << 16);
            p.y = (uint32_t)__half_as_ushort(__int2half_rn(v0.z)) |
                  ((uint32_t)__half_as_ushort(__int2half_rn(v0.w)) << 16);
            p.z = (uint32_t)__half_as_ushort(__int2half_rn(v1.x)) |
                  ((uint32_t)__half_as_ushort(__int2half_rn(v1.y)) << 16);
            p.w = (uint32_t)__half_as_ushort(__int2half_rn(v1.z)) |
                  ((uint32_t)__half_as_ushort(__int2half_rn(v1.w)) << 16);
            dw[j] = p;
        }
    }
}

// ---------------- main GEMM: mma.sync f16 (f32 acc), cp.async 3-stage -----
// 128 threads = 4 warps. CTA tile 128(M) x 128(N); warp tile 64(M) x 64(N).
// 2 CTAs/SM. The 16-LDGSTS produce burst is issued AFTER the ks0 MMA block:
// there the warp's issue slot is free and the tensor pipe holds a ~256-cycle
// backlog that fully shadows the LDGSTS issue occupancy.
__global__ void __launch_bounds__(128, 2) qgemm_kernel(
    const float* __restrict__ scale,
    const float* __restrict__ bias,
    float* __restrict__ out
) {
    extern __shared__ char smem[];
    const uint32_t sbase = smem_u32(smem);
    const int tid = threadIdx.x;
    const int m0 = blockIdx.y * MT;
    const int n0 = blockIdx.x * NT;

    const int lane = tid & 31;
    const int wid = tid >> 5;
    const int wm = wid & 1;      // M half (64 rows)
    const int wn = wid >> 1;     // N half (64 cols)

    // gmem byte-bases (row stride = KDIM * 2 bytes = 8192 = 1<<13)
    const char* pX = (const char*)g_X + ((size_t)m0 << 13);
    const char* pW = (const char*)g_W + ((size_t)n0 << 13);

    // ldmatrix address components
    const int rA = 64 * wm + (lane & 7) + ((lane >> 3) & 1) * 8;
    const int kaddA = ((lane >> 4) & 1) * 16;
    const uint32_t xmA = (uint32_t)((lane & 7) << 4);
    const int nrb = 64 * wn + (lane & 7) + ((lane >> 4) & 1) * 8;
    const int kaddB = ((lane >> 3) & 1) * 16;
    const uint32_t xmB = (uint32_t)((lane & 7) << 4);

    float acc[4][8][4];
    #pragma unroll
    for (int a = 0; a < 4; ++a)
        #pragma unroll
        for (int b = 0; b < 8; ++b)
            #pragma unroll
            for (int c = 0; c < 4; ++c) acc[a][b][c] = 0.0f;

    // ---- stage loader: A 16KB + B 16KB, 8 granule-pairs/thread ----
    auto load_stage = [&](int stg, int c) {
        const uint32_t st = sbase + (uint32_t)stg * STAGE_BYTES;
        const uint32_t ko = (uint32_t)c << 7;       // c * 128 bytes along K
        #pragma unroll
        for (int i = 0; i < 8; ++i) {               // A + B: rows 0..127 each
            const int g = tid + i * 128;
            const int row = g >> 3;
            const int col = (g & 7) << 4;
            const uint32_t soff = (uint32_t)(row * 128) + ((uint32_t)col ^ (uint32_t)((row & 7) << 4));
            const size_t goff = ((size_t)row << 13) + ko + col;
            CP16(st + soff,          pX + goff);
            CP16(st + A_TILE + soff, pW + goff);
        }
    };

    // ---- prologue: stages 0,1 ----
    load_stage(0, 0); CP_COMMIT();
    load_stage(1, 1); CP_COMMIT();

    // ---- mainloop ----
    int s_cur = 0;          // stage being computed
    int s_nxt = 2;          // stage to fill with chunk c+2
    for (int c = 0; c < NCHUNK; ++c) {
        CP_WAIT(1);
        __syncthreads();

        const uint32_t st = sbase + (uint32_t)s_cur * STAGE_BYTES;
        const uint32_t aA = st + (uint32_t)(rA * 128);
        const uint32_t aB = st + A_TILE + (uint32_t)(nrb * 128);

        uint32_t af[4][4];
        uint32_t bf[4][4];

        // ---- k-step 0: LDSM + MMA, then the produce burst under MMA shadow
        {
            const uint32_t kA = ((uint32_t)kaddA) ^ xmA;
            const uint32_t kB = ((uint32_t)kaddB) ^ xmB;
            #pragma unroll
            for (int mb = 0; mb < 4; ++mb)
                LDSM4(af[mb][0], af[mb][1], af[mb][2], af[mb][3],
                      aA + (uint32_t)(mb * 16 * 128) + kA);
            #pragma unroll
            for (int p = 0; p < 4; ++p)
                LDSM4(bf[p][0], bf[p][1], bf[p][2], bf[p][3],
                      aB + (uint32_t)(p * 16 * 128) + kB);
            #pragma unroll
            for (int mb = 0; mb < 4; ++mb) {
                #pragma unroll
                for (int nt = 0; nt < 8; ++nt) {
                    const uint32_t b0 = bf[nt >> 1][(nt & 1) * 2];
                    const uint32_t b1 = bf[nt >> 1][(nt & 1) * 2 + 1];
                    MMA_F16(acc[mb][nt], af[mb][0], af[mb][1], af[mb][2], af[mb][3], b0, b1);
                }
            }
        }

        if (c + 2 < NCHUNK) load_stage(s_nxt, c + 2);
        CP_COMMIT();

        // ---- k-steps 1..3
        #pragma unroll
        for (int ks = 1; ks < 4; ++ks) {
            const uint32_t kA = ((uint32_t)(ks * 32 + kaddA)) ^ xmA;
            const uint32_t kB = ((uint32_t)(ks * 32 + kaddB)) ^ xmB;
            #pragma unroll
            for (int mb = 0; mb < 4; ++mb)
                LDSM4(af[mb][0], af[mb][1], af[mb][2], af[mb][3],
                      aA + (uint32_t)(mb * 16 * 128) + kA);
            #pragma unroll
            for (int p = 0; p < 4; ++p)
                LDSM4(bf[p][0], bf[p][1], bf[p][2], bf[p][3],
                      aB + (uint32_t)(p * 16 * 128) + kB);
            #pragma unroll
            for (int mb = 0; mb < 4; ++mb) {
                #pragma unroll
                for (int nt = 0; nt < 8; ++nt) {
                    const uint32_t b0 = bf[nt >> 1][(nt & 1) * 2];
                    const uint32_t b1 = bf[nt >> 1][(nt & 1) * 2 + 1];
                    MMA_F16(acc[mb][nt], af[mb][0], af[mb][1], af[mb][2], af[mb][3], b0, b1);
                }
            }
        }

        // rotate stages
        s_cur = (s_cur == 2) ? 0 : s_cur + 1;
        s_nxt = (s_nxt == 2) ? 0 : s_nxt + 1;
    }

    // ---- epilogue: y = scale[n] * acc + bias[n] ----
    const int ncol = n0 + 64 * wn + 2 * (lane & 3);
    const float* scn = scale + ncol;
    const float* bin = bias + ncol;
    #pragma unroll
    for (int mb = 0; mb < 4; ++mb) {
        const int mr0 = m0 + 64 * wm + 16 * mb + (lane >> 2);
        const int mr1 = mr0 + 8;
        float* o0 = out + (size_t)mr0 * NDIM + ncol;
        float* o1 = out + (size_t)mr1 * NDIM + ncol;
        #pragma unroll
        for (int nt = 0; nt < 8; ++nt) {
            const float2 ws = *(const float2*)(scn + 8 * nt);
            const float2 bb = *(const float2*)(bin + 8 * nt);
            float2 v0, v1;
            v0.x = ws.x * acc[mb][nt][0] + bb.x;
            v0.y = ws.y * acc[mb][nt][1] + bb.y;
            v1.x = ws.x * acc[mb][nt][2] + bb.x;
            v1.y = ws.y * acc[mb][nt][3] + bb.y;
            *(float2*)(o0 + 8 * nt) = v0;
            *(float2*)(o1 + 8 * nt) = v1;
        }
    }
}

// ---------------- launcher ----------------
extern "C" void kernel_launch(void* const* d_in, const int* in_sizes, int n_in,
                              void* d_out, int out_size) {
    const float* x     = (const float*)d_in[0];
    const int*   w     = (const int*)d_in[1];
    const float* scale = (const float*)d_in[2];
    const float* bias  = (const float*)d_in[3];
    float* out = (float*)d_out;

    cudaFuncSetAttribute(qgemm_kernel, cudaFuncAttributeMaxDynamicSharedMemorySize, SMEM_BYTES);

    cvt_kernel<<<4096, 256>>>(x, w);

    dim3 grid(NDIM / NT, MDIM / MT);   // (32, 64) = 2048 CTAs
    qgemm_kernel<<<grid, 128, SMEM_BYTES>>>(scale, bias, out);
}

// round 13
// speedup vs baseline: 1.0552x; 1.0519x over previous
#include <cuda_runtime.h>
#include <cuda_fp16.h>
#include <cstdint>
#include <cstddef>

// ---------------- problem sizes ----------------
#define MDIM 8192
#define NDIM 4096
#define KDIM 4096
#define MT 128          // CTA tile M
#define NT 128          // CTA tile N
#define KC 64           // K elements per chunk (fp16 -> 128B rows)
#define NCHUNK (KDIM / KC)          // 64
#define STAGES 3
#define A_TILE 16384                // 128 rows x 128B
#define B_TILE 16384                // 128 rows x 128B
#define STAGE_BYTES (A_TILE + B_TILE)       // 32768
#define SMEM_BYTES (STAGES * STAGE_BYTES)   // 98304 -> 2 CTAs/SM

// ---------------- device scratch (no allocation allowed) ----------------
__device__ __align__(128) __half g_X[(size_t)MDIM * KDIM];
__device__ __align__(128) __half g_W[(size_t)NDIM * KDIM];

// ---------------- PTX helpers (base sm_103 target only) -------------------
static __device__ __forceinline__ uint32_t smem_u32(const void* p) {
    uint32_t a;
    asm("{ .reg .u64 t; cvta.to.shared.u64 t, %1; cvt.u32.u64 %0, t; }" : "=r"(a) : "l"(p));
    return a;
}

#define CP16(dst, src) \
    asm volatile("cp.async.cg.shared.global [%0], [%1], 16;" :: "r"((uint32_t)(dst)), "l"(src) : "memory")
#define CP_COMMIT() asm volatile("cp.async.commit_group;" ::: "memory")
#define CP_WAIT(n)  asm volatile("cp.async.wait_group %0;" :: "n"(n) : "memory")

#define LDSM4(r0, r1, r2, r3, addr) \
    asm volatile("ldmatrix.sync.aligned.m8n8.x4.shared.b16 {%0,%1,%2,%3}, [%4];" \
                 : "=r"(r0), "=r"(r1), "=r"(r2), "=r"(r3) : "r"(addr))

// f16 MMA, fp32 accumulate: D[16x8] += A[16x16] * B[16x8]
#define MMA_F16(d, a0, a1, a2, a3, b0, b1) \
    asm volatile("mma.sync.aligned.m16n8k16.row.col.f32.f16.f16.f32 " \
                 "{%0,%1,%2,%3}, {%4,%5,%6,%7}, {%8,%9}, {%0,%1,%2,%3};" \
                 : "+f"((d)[0]), "+f"((d)[1]), "+f"((d)[2]), "+f"((d)[3]) \
                 : "r"(a0), "r"(a1), "r"(a2), "r"(a3), "r"(b0), "r"(b1))

// ---------------- fused prepass: x fp32->fp16, w int32->fp16 --------------
// 8 elements per thread per iteration: two 16B loads -> one 16B store.
#define NX8 ((size_t)MDIM * KDIM / 8)
#define NW8 ((size_t)NDIM * KDIM / 8)
__global__ void __launch_bounds__(256) cvt_kernel(const float* __restrict__ x,
                                                  const int* __restrict__ w) {
    const float4* __restrict__ x4 = (const float4*)x;
    const int4* __restrict__ w4 = (const int4*)w;
    uint4* __restrict__ dx = (uint4*)g_X;
    uint4* __restrict__ dw = (uint4*)g_W;
    const size_t total = NX8 + NW8;
    size_t stride = (size_t)gridDim.x * blockDim.x;
    for (size_t i = (size_t)blockIdx.x * blockDim.x + threadIdx.x; i < total; i += stride) {
        uint4 p;
        if (i < NX8) {
            float4 v0 = x4[2 * i];
            float4 v1 = x4[2 * i + 1];
            p.x = (uint32_t)__half_as_ushort(__float2half_rn(v0.x)) |
                  ((uint32_t)__half_as_ushort(__float2half_rn(v0.y)) << 16);
            p.y = (uint32_t)__half_as_ushort(__float2half_rn(v0.z)) |
                  ((uint32_t)__half_as_ushort(__float2half_rn(v0.w)) << 16);
            p.z = (uint32_t)__half_as_ushort(__float2half_rn(v1.x)) |
                  ((uint32_t)__half_as_ushort(__float2half_rn(v1.y)) << 16);
            p.w = (uint32_t)__half_as_ushort(__float2half_rn(v1.z)) |
                  ((uint32_t)__half_as_ushort(__float2half_rn(v1.w)) << 16);
            dx[i] = p;
        } else {
            const size_t j = i - NX8;
            int4 v0 = w4[2 * j];
            int4 v1 = w4[2 * j + 1];
            p.x = (uint32_t)__half_as_ushort(__int2half_rn(v0.x)) |
                  ((uint32_t)__half_as_ushort(__int2half_rn(v0.y)) << 16);
            p.y = (uint32_t)__half_as_ushort(__int2half_rn(v0.z)) |
                  ((uint32_t)__half_as_ushort(__int2half_rn(v0.w)) << 16);
            p.z = (uint32_t)__half_as_ushort(__int2half_rn(v1.x)) |
                  ((uint32_t)__half_as_ushort(__int2half_rn(v1.y)) << 16);
            p.w = (uint32_t)__half_as_ushort(__int2half_rn(v1.z)) |
                  ((uint32_t)__half_as_ushort(__int2half_rn(v1.w)) << 16);
            dw[j] = p;
        }
    }
}

// ---------------- main GEMM: mma.sync f16 (f32 acc), cp.async 3-stage -----
// 128 threads = 4 warps. CTA tile 128(M) x 128(N); warp tile 64(M) x 64(N).
// 2 CTAs/SM. Cross-chunk fragment prefetch: each iteration ends with
// CP_WAIT+barrier followed by the NEXT chunk's ks0 ldmatrix, issued under the
// ks3 MMA backlog — so at the next iteration top MMAs issue immediately and
// the tensor pipe never drains across the chunk boundary.
__global__ void __launch_bounds__(128, 2) qgemm_kernel(
    const float* __restrict__ scale,
    const float* __restrict__ bias,
    float* __restrict__ out
) {
    extern __shared__ char smem[];
    const uint32_t sbase = smem_u32(smem);
    const int tid = threadIdx.x;
    const int m0 = blockIdx.y * MT;
    const int n0 = blockIdx.x * NT;

    const int lane = tid & 31;
    const int wid = tid >> 5;
    const int wm = wid & 1;      // M half (64 rows)
    const int wn = wid >> 1;     // N half (64 cols)

    // gmem byte-bases (row stride = KDIM * 2 bytes = 8192 = 1<<13)
    const char* pX = (const char*)g_X + ((size_t)m0 << 13);
    const char* pW = (const char*)g_W + ((size_t)n0 << 13);

    // ldmatrix address components
    const int rA = 64 * wm + (lane & 7) + ((lane >> 3) & 1) * 8;
    const int kaddA = ((lane >> 4) & 1) * 16;
    const uint32_t xmA = (uint32_t)((lane & 7) << 4);
    const int nrb = 64 * wn + (lane & 7) + ((lane >> 4) & 1) * 8;
    const int kaddB = ((lane >> 3) & 1) * 16;
    const uint32_t xmB = (uint32_t)((lane & 7) << 4);
    const uint32_t kA0 = ((uint32_t)kaddA) ^ xmA;
    const uint32_t kB0 = ((uint32_t)kaddB) ^ xmB;

    float acc[4][8][4];
    #pragma unroll
    for (int a = 0; a < 4; ++a)
        #pragma unroll
        for (int b = 0; b < 8; ++b)
            #pragma unroll
            for (int c = 0; c < 4; ++c) acc[a][b][c] = 0.0f;

    // ---- stage loader: A 16KB + B 16KB, 8 granule-pairs/thread ----
    auto load_stage = [&](int stg, int c) {
        const uint32_t st = sbase + (uint32_t)stg * STAGE_BYTES;
        const uint32_t ko = (uint32_t)c << 7;       // c * 128 bytes along K
        #pragma unroll
        for (int i = 0; i < 8; ++i) {               // A + B: rows 0..127 each
            const int g = tid + i * 128;
            const int row = g >> 3;
            const int col = (g & 7) << 4;
            const uint32_t soff = (uint32_t)(row * 128) + ((uint32_t)col ^ (uint32_t)((row & 7) << 4));
            const size_t goff = ((size_t)row << 13) + ko + col;
            CP16(st + soff,          pX + goff);
            CP16(st + A_TILE + soff, pW + goff);
        }
    };

    uint32_t af[4][4];
    uint32_t bf[4][4];

    // ks0 fragment loader from a given stage base
    auto ldsm_ks0 = [&](uint32_t st) {
        const uint32_t aA = st + (uint32_t)(rA * 128);
        const uint32_t aB = st + A_TILE + (uint32_t)(nrb * 128);
        #pragma unroll
        for (int mb = 0; mb < 4; ++mb)
            LDSM4(af[mb][0], af[mb][1], af[mb][2], af[mb][3],
                  aA + (uint32_t)(mb * 16 * 128) + kA0);
        #pragma unroll
        for (int p = 0; p < 4; ++p)
            LDSM4(bf[p][0], bf[p][1], bf[p][2], bf[p][3],
                  aB + (uint32_t)(p * 16 * 128) + kB0);
    };

    // ---- prologue: stages 0,1; prefetch ks0 of chunk 0 ----
    load_stage(0, 0); CP_COMMIT();
    load_stage(1, 1); CP_COMMIT();
    CP_WAIT(1);
    __syncthreads();
    ldsm_ks0(sbase);

    // ---- mainloop ----
    int s_cur = 0;          // stage of chunk c
    int s_nxt = 2;          // stage to fill with chunk c+2
    for (int c = 0; c < NCHUNK; ++c) {
        const uint32_t st = sbase + (uint32_t)s_cur * STAGE_BYTES;
        const uint32_t aA = st + (uint32_t)(rA * 128);
        const uint32_t aB = st + A_TILE + (uint32_t)(nrb * 128);

        // ---- ks0 MMAs from prefetched fragments (pipe fills immediately)
        #pragma unroll
        for (int mb = 0; mb < 4; ++mb) {
            #pragma unroll
            for (int nt = 0; nt < 8; ++nt) {
                const uint32_t b0 = bf[nt >> 1][(nt & 1) * 2];
                const uint32_t b1 = bf[nt >> 1][(nt & 1) * 2 + 1];
                MMA_F16(acc[mb][nt], af[mb][0], af[mb][1], af[mb][2], af[mb][3], b0, b1);
            }
        }

        // ---- produce burst under the ks0 MMA backlog
        if (c + 2 < NCHUNK) load_stage(s_nxt, c + 2);
        CP_COMMIT();

        // ---- k-steps 1..3
        #pragma unroll
        for (int ks = 1; ks < 4; ++ks) {
            const uint32_t kA = ((uint32_t)(ks * 32 + kaddA)) ^ xmA;
            const uint32_t kB = ((uint32_t)(ks * 32 + kaddB)) ^ xmB;
            #pragma unroll
            for (int mb = 0; mb < 4; ++mb)
                LDSM4(af[mb][0], af[mb][1], af[mb][2], af[mb][3],
                      aA + (uint32_t)(mb * 16 * 128) + kA);
            #pragma unroll
            for (int p = 0; p < 4; ++p)
                LDSM4(bf[p][0], bf[p][1], bf[p][2], bf[p][3],
                      aB + (uint32_t)(p * 16 * 128) + kB);
            #pragma unroll
            for (int mb = 0; mb < 4; ++mb) {
                #pragma unroll
                for (int nt = 0; nt < 8; ++nt) {
                    const uint32_t b0 = bf[nt >> 1][(nt & 1) * 2];
                    const uint32_t b1 = bf[nt >> 1][(nt & 1) * 2 + 1];
                    MMA_F16(acc[mb][nt], af[mb][0], af[mb][1], af[mb][2], af[mb][3], b0, b1);
                }
            }
        }

        // ---- end of iter: guarantee chunk c+1 data, then prefetch its ks0
        // (ks3 MMA backlog covers the wait+barrier+LDSM latency)
        CP_WAIT(1);
        __syncthreads();
        s_cur = (s_cur == 2) ? 0 : s_cur + 1;
        s_nxt = (s_nxt == 2) ? 0 : s_nxt + 1;
        if (c + 1 < NCHUNK)
            ldsm_ks0(sbase + (uint32_t)s_cur * STAGE_BYTES);
    }

    // ---- epilogue: y = scale[n] * acc + bias[n] ----
    const int ncol = n0 + 64 * wn + 2 * (lane & 3);
    const float* scn = scale + ncol;
    const float* bin = bias + ncol;
    #pragma unroll
    for (int mb = 0; mb < 4; ++mb) {
        const int mr0 = m0 + 64 * wm + 16 * mb + (lane >> 2);
        const int mr1 = mr0 + 8;
        float* o0 = out + (size_t)mr0 * NDIM + ncol;
        float* o1 = out + (size_t)mr1 * NDIM + ncol;
        #pragma unroll
        for (int nt = 0; nt < 8; ++nt) {
            const float2 ws = *(const float2*)(scn + 8 * nt);
            const float2 bb = *(const float2*)(bin + 8 * nt);
            float2 v0, v1;
            v0.x = ws.x * acc[mb][nt][0] + bb.x;
            v0.y = ws.y * acc[mb][nt][1] + bb.y;
            v1.x = ws.x * acc[mb][nt][2] + bb.x;
            v1.y = ws.y * acc[mb][nt][3] + bb.y;
            *(float2*)(o0 + 8 * nt) = v0;
            *(float2*)(o1 + 8 * nt) = v1;
        }
    }
}

// ---------------- launcher ----------------
extern "C" void kernel_launch(void* const* d_in, const int* in_sizes, int n_in,
                              void* d_out, int out_size) {
    const float* x     = (const float*)d_in[0];
    const int*   w     = (const int*)d_in[1];
    const float* scale = (const float*)d_in[2];
    const float* bias  = (const float*)d_in[3];
    float* out = (float*)d_out;

    cudaFuncSetAttribute(qgemm_kernel, cudaFuncAttributeMaxDynamicSharedMemorySize, SMEM_BYTES);

    cvt_kernel<<<4096, 256>>>(x, w);

    dim3 grid(NDIM / NT, MDIM / MT);   // (32, 64) = 2048 CTAs
    qgemm_kernel<<<grid, 128, SMEM_BYTES>>>(scale, bias, out);
}